// round 6
// baseline (speedup 1.0000x reference)
#include <cuda_runtime.h>
#include <math.h>
#include <float.h>

#define OUTD    12
#define N_VOX   1728              // 12*12*12
#define N_ROIS  128
#define N_PTS   160000
#define NCH     64
#define KMAX    64                // cap on points per (roi,voxel); fallback handles overflow
#define NRV     (N_ROIS * N_VOX)  // 221184 = 864 * 256

#define BQ      320               // build block size (2 pts/thread)
#define HALF    (N_PTS / 2)       // 80000
static_assert(HALF % BQ == 0, "exact build grid");
static_assert(NRV % 256 == 0, "exact pool grid");

// Scratch (__device__ globals = sanctioned scratch; zero-initialized at load).
// d_count is self-cleaned by pool_kernel each run -> invariant holds across replays.
__device__ int d_count[NRV];
__device__ __align__(16) int d_list[NRV * KMAX];   // 16B align for int4 loads

// ---------------------------------------------------------------------------
// Full in-box test + list push for one candidate point (circle test passed).
// ---------------------------------------------------------------------------
__device__ __forceinline__ void test_and_push(
    int r, int p, float sx, float sy, float pz,
    const float4* sA, const float4* sB, const float4* sC)
{
    float4 A = sA[r];
    float4 B = sB[r];
    float4 C = sC[r];
    float sz = pz - A.w;
    float lx = sx * B.x - sy * B.y;           // rotate into roi frame (angle = -ry)
    float ly = sx * B.y + sy * B.x;
    bool in_box = (lx > -B.z) && (lx < B.z) &&
                  (ly > -B.w) && (ly < B.w) &&
                  (fabsf(sz - C.x) <= C.x);
    if (!in_box) return;
    int xi = min(OUTD - 1, max(0, (int)floorf((lx + B.z) / C.y)));
    int yi = min(OUTD - 1, max(0, (int)floorf((ly + B.w) / C.z)));
    int zi = min(OUTD - 1, max(0, (int)floorf(sz / C.w)));
    int rv = r * N_VOX + xi * (OUTD * OUTD) + yi * OUTD + zi;
    int c = atomicAdd(&d_count[rv], 1);
    if (c < KMAX) d_list[rv * KMAX + c] = p;
}

// ---------------------------------------------------------------------------
// Kernel 1: TWO points per thread, warp-uniform loop over 128 ROIs.
// One LDS.128 serves both points; skip branch taken only when BOTH miss
// (still ~99.5% of iters). No output zero-fill here (pool does it) so
// d_count/d_list stay L2-resident for pool.
// ---------------------------------------------------------------------------
__global__ __launch_bounds__(BQ) void build_lists_kernel(
    const float* __restrict__ rois, const float* __restrict__ pts)
{
    __shared__ float4 sA[N_ROIS];  // {cx, cy, r2_margin, cz}
    __shared__ float4 sB[N_ROIS];  // {cosa, sina, hdx, hdy}
    __shared__ float4 sC[N_ROIS];  // {hdz, vx, vy, vz}

    int t = threadIdx.x;
    int p0 = blockIdx.x * BQ + t;             // < 80000
    int p1 = p0 + HALF;                       // second point, also coalesced

    float px0 = pts[3 * p0 + 0], py0 = pts[3 * p0 + 1], pz0 = pts[3 * p0 + 2];
    float px1 = pts[3 * p1 + 0], py1 = pts[3 * p1 + 1], pz1 = pts[3 * p1 + 2];

    if (t < N_ROIS) {
        const float* R = rois + t * 7;
        float cx = R[0], cy = R[1], cz = R[2];
        float dx = R[3], dy = R[4], dz = R[5];
        float ry = R[6];
        float hdx = dx * 0.5f, hdy = dy * 0.5f, hdz = dz * 0.5f;
        float r2  = (hdx * hdx + hdy * hdy) * 1.0002f + 1e-6f;  // conservative
        float ca  = cosf(-ry), sa = sinf(-ry);
        sA[t] = make_float4(cx, cy, r2, cz);
        sB[t] = make_float4(ca, sa, hdx, hdy);
        sC[t] = make_float4(hdz, dx / (float)OUTD, dy / (float)OUTD, dz / (float)OUTD);
    }
    __syncthreads();

    #pragma unroll 4
    for (int r = 0; r < N_ROIS; r++) {
        float4 A = sA[r];                     // broadcast LDS.128 (uniform r)
        float sx0 = px0 - A.x, sy0 = py0 - A.y;
        float sx1 = px1 - A.x, sy1 = py1 - A.y;
        float d20 = sx0 * sx0 + sy0 * sy0;
        float d21 = sx1 * sx1 + sy1 * sy1;
        bool c0 = (d20 <= A.z), c1 = (d21 <= A.z);
        if (!(c0 | c1)) continue;             // ~99.5% skip
        if (c0) test_and_push(r, p0, sx0, sy0, pz0, sA, sB, sC);
        if (c1) test_and_push(r, p1, sx1, sy1, pz1, sA, sB, sC);
    }
}

// ---------------------------------------------------------------------------
// Kernel 2: block = 256 voxels, __launch_bounds__(256,6) -> regs<=42 ->
// 6 blocks/SM -> all 864 blocks in ONE wave. Coalesced count scan into smem
// (+ self-clean), warp sweep writes zeros for empty voxels (fire-and-forget,
// warp-uniform branch), ballot-compacted queue of non-empty voxels processed
// with a 2-deep pipeline (metadata now L2-hot: no zero-fill evicted it).
// ---------------------------------------------------------------------------
__global__ __launch_bounds__(256, 6) void pool_kernel(
    const float* __restrict__ rois, const float* __restrict__ pts,
    const float* __restrict__ feat, float* __restrict__ out)
{
    __shared__ int sCnt[256];
    __shared__ int sQ[256];
    __shared__ int sQn;

    int t    = threadIdx.x;
    int lane = t & 31;
    int wid  = t >> 5;
    int vblock = blockIdx.x << 8;             // first voxel of this block

    int c = d_count[vblock + t];              // coalesced 1KB burst (L2-hot)
    sCnt[t] = c;
    if (c) d_count[vblock + t] = 0;           // self-clean only dirty entries
    if (t == 0) sQn = 0;
    __syncthreads();

    // Ballot-compact non-empty local voxel ids into sQ.
    unsigned m = __ballot_sync(0xffffffffu, c > 0);
    int base = 0;
    if (lane == 0 && m) base = atomicAdd(&sQn, __popc(m));
    base = __shfl_sync(0xffffffffu, base, 0);
    if (c > 0) sQ[base + __popc(m & ((1u << lane) - 1u))] = t;

    // Zero-fill this warp's 32 voxels where empty (fire-and-forget STG.64,
    // warp-uniform branch via smem broadcast). ~29-30 of 32 voxels.
    int kbase = wid << 5;
    float2 z2 = make_float2(0.f, 0.f);
    #pragma unroll 4
    for (int k = 0; k < 32; k++) {
        if (sCnt[kbase + k] == 0)
            ((float2*)(out + (size_t)(vblock + kbase + k) * NCH))[lane] = z2;
    }
    __syncthreads();
    int qn = sQn;

    // Warps grab non-empty entries strided; 2-deep pipeline hides list latency.
    int i = wid;
    int nGv = -1, nN = 0;
    int4 nP4 = make_int4(0, 0, 0, 0);
    if (i < qn) {
        int lv = sQ[i];
        nGv = vblock + lv;
        nN  = sCnt[lv];
        nP4 = *(const int4*)&d_list[(size_t)nGv * KMAX];
    }
    while (nGv >= 0) {
        int gv = nGv, n = nN;
        int4 p4 = nP4;
        i += 8;
        if (i < qn) {
            int lv = sQ[i];
            nGv = vblock + lv;
            nN  = sCnt[lv];
            nP4 = *(const int4*)&d_list[(size_t)nGv * KMAX];   // prefetch next
        } else {
            nGv = -1;
        }

        float mx0 = -FLT_MAX, mx1 = -FLT_MAX;
        int mm = min(n, KMAX);
        {   // up to 4 independent feature-row loads (MLP), predicated
            float2 v0, v1, v2, v3;
            if (mm > 0) v0 = ((const float2*)(feat + (size_t)p4.x * NCH))[lane];
            if (mm > 1) v1 = ((const float2*)(feat + (size_t)p4.y * NCH))[lane];
            if (mm > 2) v2 = ((const float2*)(feat + (size_t)p4.z * NCH))[lane];
            if (mm > 3) v3 = ((const float2*)(feat + (size_t)p4.w * NCH))[lane];
            if (mm > 0) { mx0 = fmaxf(mx0, v0.x); mx1 = fmaxf(mx1, v0.y); }
            if (mm > 1) { mx0 = fmaxf(mx0, v1.x); mx1 = fmaxf(mx1, v1.y); }
            if (mm > 2) { mx0 = fmaxf(mx0, v2.x); mx1 = fmaxf(mx1, v2.y); }
            if (mm > 3) { mx0 = fmaxf(mx0, v3.x); mx1 = fmaxf(mx1, v3.y); }
        }
        const int* lst = &d_list[(size_t)gv * KMAX];
        for (int j = 4; j < mm; j++) {        // rare (P(n>4) tiny)
            int pid = lst[j];
            float2 v = ((const float2*)(feat + (size_t)pid * NCH))[lane];
            mx0 = fmaxf(mx0, v.x);
            mx1 = fmaxf(mx1, v.y);
        }

        if (n > KMAX) {
            // Correctness fallback (statistically never taken): rescan all
            // points. n is warp-uniform so the whole warp enters together.
            int r = gv / N_VOX, vox = gv % N_VOX;
            int xi = vox / (OUTD * OUTD), yi = (vox / OUTD) % OUTD, zi = vox % OUTD;
            const float* R = rois + r * 7;
            float cx = R[0], cy = R[1], cz = R[2];
            float dx = R[3], dy = R[4], dz = R[5];
            float ry = R[6];
            float hdx = dx * 0.5f, hdy = dy * 0.5f, hdz = dz * 0.5f;
            float ca = cosf(-ry), sa = sinf(-ry);
            float vx = dx / (float)OUTD, vy = dy / (float)OUTD, vz = dz / (float)OUTD;
            for (int bb = 0; bb < N_PTS; bb += 32) {
                int pp = bb + lane;
                bool hit = false;
                {
                    float sx = pts[3 * pp + 0] - cx;
                    float sy = pts[3 * pp + 1] - cy;
                    float szz = pts[3 * pp + 2] - cz;
                    float lx = sx * ca - sy * sa;
                    float ly = sx * sa + sy * ca;
                    if ((lx > -hdx) && (lx < hdx) && (ly > -hdy) && (ly < hdy) &&
                        (fabsf(szz - hdz) <= hdz)) {
                        int xa = min(OUTD - 1, max(0, (int)floorf((lx + hdx) / vx)));
                        int ya = min(OUTD - 1, max(0, (int)floorf((ly + hdy) / vy)));
                        int za = min(OUTD - 1, max(0, (int)floorf(szz / vz)));
                        hit = (xa == xi) && (ya == yi) && (za == zi);
                    }
                }
                unsigned mk = __ballot_sync(0xffffffffu, hit);
                while (mk) {
                    int src = __ffs(mk) - 1;
                    mk &= mk - 1;
                    int pid = bb + src;
                    float2 v = ((const float2*)(feat + (size_t)pid * NCH))[lane];
                    mx0 = fmaxf(mx0, v.x);
                    mx1 = fmaxf(mx1, v.y);
                }
            }
        }

        float2* o = (float2*)(out + (size_t)gv * NCH);
        o[lane] = make_float2(mx0, mx1);
    }
}

// ---------------------------------------------------------------------------
extern "C" void kernel_launch(void* const* d_in, const int* in_sizes, int n_in,
                              void* d_out, int out_size)
{
    const float* rois = (const float*)d_in[0];       // (128, 7)
    const float* pts  = (const float*)d_in[1];       // (160000, 3)
    const float* feat = (const float*)d_in[2];       // (160000, 64)
    float* out = (float*)d_out;                      // (128, 12, 12, 12, 64)

    build_lists_kernel<<<HALF / BQ, BQ>>>(rois, pts);       // 250 blocks, 2 pts/thread
    pool_kernel<<<NRV / 256, 256>>>(rois, pts, feat, out);  // 864 blocks, one wave
}